// round 10
// baseline (speedup 1.0000x reference)
#include <cuda_runtime.h>
#include <cuda_fp16.h>
#include <math.h>

// GraphSAGE 3-layer, N=100000, E=3200000, D: 64 -> 64 -> 32 -> 1
// CSR-gather aggregation, fp16 gather sources (fp32 accumulate).
// R9: mega-fused combine1 computes h1 in smem and immediately produces both
// layer-2 projections (p2 = h1@W2l fp16, r2 = h1@W2r fp32); g_h1 and the
// separate proj2h pass are eliminated; combine2 is now elementwise+reduce.

#define NMAX 100000
#define EMAX 3200000
#define SCAN_TB 1024
#define NBLK ((NMAX + SCAN_TB - 1) / SCAN_TB)

__device__ __align__(16) float   g_agg[NMAX * 64];  // aggregated means (fp32)
__device__ __align__(16) __half2 g_xh[NMAX * 32];   // x in fp16 (64 per node)
__device__ __align__(16) __half2 g_p2[NMAX * 16];   // h1@W2l in fp16 (32 per node)
__device__ __align__(16) float   g_r2[NMAX * 32];   // h1@W2r in fp32 (self term, 32 per node)
__device__ float g_p3[NMAX];                        // h2 @ W3l
__device__ float g_r3[NMAX];                        // h2 @ W3r (self term)
__device__ float g_inv[NMAX];                       // 1 / max(deg, 1)
__device__ int   g_deg[NMAX];
__device__ int   g_start[NMAX];
__device__ int   g_fill[NMAX];
__device__ int   g_bsum[NBLK + 1];
__device__ int   g_csr[EMAX];                       // src ids bucketed by dst

// ---------------- CSR build ----------------

__global__ void zero_deg_kernel(int N) {
    int i = blockIdx.x * blockDim.x + threadIdx.x;
    if (i < N) g_deg[i] = 0;
}

__global__ void hist_kernel(const int* __restrict__ dst, int E) {
    int e = blockIdx.x * blockDim.x + threadIdx.x;
    if (e < E) atomicAdd(&g_deg[dst[e]], 1);
}

__global__ void blocksum_kernel(int N) {
    __shared__ int sred[SCAN_TB];
    int i = blockIdx.x * SCAN_TB + threadIdx.x;
    int d = (i < N) ? g_deg[i] : 0;
    sred[threadIdx.x] = d;
    __syncthreads();
    for (int off = SCAN_TB / 2; off > 0; off >>= 1) {
        if (threadIdx.x < off) sred[threadIdx.x] += sred[threadIdx.x + off];
        __syncthreads();
    }
    if (threadIdx.x == 0) g_bsum[blockIdx.x] = sred[0];
}

__global__ void scan_bsums_kernel(int nb) {
    if (threadIdx.x == 0) {
        int acc = 0;
        for (int i = 0; i < nb; i++) {
            int v = g_bsum[i];
            g_bsum[i] = acc;
            acc += v;
        }
    }
}

__global__ void starts_kernel(int N) {
    __shared__ int stmp[SCAN_TB];
    int i = blockIdx.x * SCAN_TB + threadIdx.x;
    int d = (i < N) ? g_deg[i] : 0;
    stmp[threadIdx.x] = d;
    __syncthreads();
    for (int off = 1; off < SCAN_TB; off <<= 1) {
        int v = (threadIdx.x >= off) ? stmp[threadIdx.x - off] : 0;
        __syncthreads();
        stmp[threadIdx.x] += v;
        __syncthreads();
    }
    if (i < N) {
        int excl = stmp[threadIdx.x] - d + g_bsum[blockIdx.x];
        g_start[i] = excl;
        g_inv[i] = 1.0f / fmaxf((float)d, 1.0f);
        g_fill[i] = 0;
    }
}

__global__ void place_kernel(const int* __restrict__ src,
                             const int* __restrict__ dst, int E) {
    int e = blockIdx.x * blockDim.x + threadIdx.x;
    if (e >= E) return;
    int d = dst[e];
    int pos = g_start[d] + atomicAdd(&g_fill[d], 1);
    g_csr[pos] = src[e];
}

// ---------------- fp16 conversion ----------------

__global__ void convert_x_kernel(const float* __restrict__ x, int N) {
    int t = blockIdx.x * blockDim.x + threadIdx.x;
    if (t >= N * 32) return;
    float2 v = ((const float2*)x)[t];
    g_xh[t] = __floats2half2_rn(v.x, v.y);
}

// ---------------- gathers (mean, fp16 sources, fp32 accumulate) ----------------

// 64-d: one warp per node, lane owns one half2. Row = 128B. Unroll 8 for MLP.
__global__ void gather64h_kernel(int N) {
    int g = blockIdx.x * blockDim.x + threadIdx.x;
    int node = g >> 5;
    int lane = g & 31;
    if (node >= N) return;
    int s0 = g_start[node];
    int d = g_deg[node];
    float ax = 0.f, ay = 0.f;
    int j = 0;
    for (; j + 8 <= d; j += 8) {
        int si[8];
#pragma unroll
        for (int u = 0; u < 8; u++) si[u] = g_csr[s0 + j + u];
        __half2 v[8];
#pragma unroll
        for (int u = 0; u < 8; u++) v[u] = g_xh[si[u] * 32 + lane];
#pragma unroll
        for (int u = 0; u < 8; u++) {
            float2 f = __half22float2(v[u]);
            ax += f.x;
            ay += f.y;
        }
    }
    for (; j < d; j++) {
        float2 f = __half22float2(g_xh[g_csr[s0 + j] * 32 + lane]);
        ax += f.x;
        ay += f.y;
    }
    float iv = g_inv[node];
    ((float2*)g_agg)[node * 32 + lane] = make_float2(ax * iv, ay * iv);
}

// 32-d: two nodes per warp, 16 lanes per node, lane owns one half2. Row = 64B.
__global__ void gather32h_kernel(int N) {
    int g = blockIdx.x * blockDim.x + threadIdx.x;
    int node = g >> 4;
    int lane = g & 15;
    if (node >= N) return;
    int s0 = g_start[node];
    int d = g_deg[node];
    float ax = 0.f, ay = 0.f;
    int j = 0;
    for (; j + 8 <= d; j += 8) {
        int si[8];
#pragma unroll
        for (int u = 0; u < 8; u++) si[u] = g_csr[s0 + j + u];
        __half2 v[8];
#pragma unroll
        for (int u = 0; u < 8; u++) v[u] = g_p2[si[u] * 16 + lane];
#pragma unroll
        for (int u = 0; u < 8; u++) {
            float2 f = __half22float2(v[u]);
            ax += f.x;
            ay += f.y;
        }
    }
    for (; j < d; j++) {
        float2 f = __half22float2(g_p2[g_csr[s0 + j] * 16 + lane]);
        ax += f.x;
        ay += f.y;
    }
    float iv = g_inv[node];
    ((float2*)g_agg)[node * 16 + lane] = make_float2(ax * iv, ay * iv);
}

// ---------------- mega-fused layer-1 combine + layer-2 projections ----------------
// Phase A: h1[node,o] = relu(mean@W1l + b1 + x@W1r)  -> smem (4 nodes/block)
// Phase B: p2[node,q] = fp16(h1@W2l[:,q]);  r2[node,q] = h1@W2r[:,q]
__global__ void combine1_mega_kernel(const float* __restrict__ W1l,
                                     const float* __restrict__ b1,
                                     const float* __restrict__ x,
                                     const float* __restrict__ W1r,
                                     const float* __restrict__ W2l,
                                     const float* __restrict__ W2r, int N) {
    __shared__ float sWl[64 * 64];
    __shared__ float sWr[64 * 64];
    __shared__ float sW2l[64 * 32];
    __shared__ float sW2r[64 * 32];
    __shared__ float sb[64];
    __shared__ float sh1[4][64];
    for (int i = threadIdx.x; i < 64 * 64; i += blockDim.x) {
        sWl[i] = W1l[i];
        sWr[i] = W1r[i];
    }
    for (int i = threadIdx.x; i < 64 * 32; i += blockDim.x) {
        sW2l[i] = W2l[i];
        sW2r[i] = W2r[i];
    }
    if (threadIdx.x < 64) sb[threadIdx.x] = b1[threadIdx.x];
    __syncthreads();

    int t = blockIdx.x * blockDim.x + threadIdx.x;
    int node = t >> 6;
    int ln = (threadIdx.x >> 6);  // local node 0..3
    int o = threadIdx.x & 63;

    if (node < N) {
        const float* xr = x + (long long)node * 64;
        const float* mr = g_agg + (long long)node * 64;
        float acc = sb[o];
#pragma unroll
        for (int k = 0; k < 64; k++) {
            acc = fmaf(mr[k], sWl[k * 64 + o], acc);
            acc = fmaf(xr[k], sWr[k * 64 + o], acc);
        }
        sh1[ln][o] = fmaxf(acc, 0.f);
    }
    __syncthreads();

    // Phase B: 64 outputs per node (32 p2 + 32 r2), one per thread.
    if (node < N) {
        int q = o & 31;
        const float* W = (o < 32) ? sW2l : sW2r;
        float acc = 0.f;
#pragma unroll
        for (int k = 0; k < 64; k++) acc = fmaf(sh1[ln][k], W[k * 32 + q], acc);
        if (o < 32)
            ((__half*)g_p2)[node * 32 + q] = __float2half_rn(acc);
        else
            g_r2[node * 32 + q] = acc;
    }
}

// Layer-2 combine (elementwise) + both layer-3 dots. One warp per node.
__global__ void combine2_small_kernel(const float* __restrict__ b2,
                                      const float* __restrict__ W3l,
                                      const float* __restrict__ W3r, int N) {
    __shared__ float sb[32], s3l[32], s3r[32];
    if (threadIdx.x < 32) {
        sb[threadIdx.x] = b2[threadIdx.x];
        s3l[threadIdx.x] = W3l[threadIdx.x];
        s3r[threadIdx.x] = W3r[threadIdx.x];
    }
    __syncthreads();
    int g = blockIdx.x * blockDim.x + threadIdx.x;
    int node = g >> 5;
    int lane = g & 31;
    if (node >= N) return;
    float h2 = fmaxf(g_agg[node * 32 + lane] + sb[lane] + g_r2[node * 32 + lane], 0.f);
    float a = h2 * s3l[lane];
    float r = h2 * s3r[lane];
#pragma unroll
    for (int off = 16; off; off >>= 1) {
        a += __shfl_xor_sync(0xffffffffu, a, off);
        r += __shfl_xor_sync(0xffffffffu, r, off);
    }
    if (lane == 0) {
        g_p3[node] = a;
        g_r3[node] = r;
    }
}

// Final: one warp per node, lanes parallel over edges; fused sigmoid.
__global__ void gather1_final_kernel(const float* __restrict__ b3,
                                     float* __restrict__ out, int N) {
    int g = blockIdx.x * blockDim.x + threadIdx.x;
    int node = g >> 5;
    int lane = g & 31;
    if (node >= N) return;
    int s0 = g_start[node];
    int d = g_deg[node];
    float acc = 0.f;
    for (int j = lane; j < d; j += 32) acc += g_p3[g_csr[s0 + j]];
#pragma unroll
    for (int off = 16; off; off >>= 1) acc += __shfl_xor_sync(0xffffffffu, acc, off);
    if (lane == 0) {
        float v = acc * g_inv[node] + b3[0] + g_r3[node];
        out[node] = 1.0f / (1.0f + expf(-v));
    }
}

// ---------------- launch ----------------

extern "C" void kernel_launch(void* const* d_in, const int* in_sizes, int n_in,
                              void* d_out, int out_size) {
    const float* x   = (const float*)d_in[0];
    const int*   ei  = (const int*)d_in[1];   // int32 (JAX x64 disabled)
    const float* W1l = (const float*)d_in[2];
    const float* b1  = (const float*)d_in[3];
    const float* W1r = (const float*)d_in[4];
    const float* W2l = (const float*)d_in[5];
    const float* b2  = (const float*)d_in[6];
    const float* W2r = (const float*)d_in[7];
    const float* W3l = (const float*)d_in[8];
    const float* b3  = (const float*)d_in[9];
    const float* W3r = (const float*)d_in[10];
    float* out = (float*)d_out;

    int N = in_sizes[0] / 64;
    int E = in_sizes[1] / 2;
    const int* src = ei;
    const int* dst = ei + E;

    const int TB = 256;
    auto blocks = [](long long n, int tb) { return (int)((n + tb - 1) / tb); };
    int nb = (N + SCAN_TB - 1) / SCAN_TB;

    // CSR build (reused by all 3 layers); convert x to fp16 concurrently.
    zero_deg_kernel<<<blocks(N, TB), TB>>>(N);
    hist_kernel<<<blocks(E, TB), TB>>>(dst, E);
    convert_x_kernel<<<blocks((long long)N * 32, TB), TB>>>(x, N);
    blocksum_kernel<<<nb, SCAN_TB>>>(N);
    scan_bsums_kernel<<<1, 32>>>(nb);
    starts_kernel<<<nb, SCAN_TB>>>(N);
    place_kernel<<<blocks(E, TB), TB>>>(src, dst, E);

    // ---- layer 1: gather raw x (fp16); mega combine emits p2 (fp16) + r2 ----
    gather64h_kernel<<<blocks((long long)N * 32, TB), TB>>>(N);
    combine1_mega_kernel<<<blocks((long long)N * 64, TB), TB>>>(
        W1l, b1, x, W1r, W2l, W2r, N);

    // ---- layer 2: gather p2, tiny combine + layer-3 dots ----
    gather32h_kernel<<<blocks((long long)N * 16, TB), TB>>>(N);
    combine2_small_kernel<<<blocks((long long)N * 32, TB), TB>>>(b2, W3l, W3r, N);

    // ---- layer 3: scalar gather + sigmoid ----
    gather1_final_kernel<<<blocks((long long)N * 32, TB), TB>>>(b3, out, N);
}

// round 11
// speedup vs baseline: 2.0411x; 2.0411x over previous
#include <cuda_runtime.h>
#include <cuda_fp16.h>
#include <mma.h>
#include <math.h>

using namespace nvcuda;

// GraphSAGE 3-layer, N=100000, E=3200000, D: 64 -> 64 -> 32 -> 1
// CSR-gather aggregation (fp16 sources, fp32 accumulate) + tensor-core (wmma)
// fused dense chain: H1 -> P2/R2 in one kernel, h1 never materialized in gmem.

#define NMAX 100000
#define NPAD 100096   // padded to 64-node tiles for wmma loads
#define EMAX 3200000
#define SCAN_TB 1024
#define NBLK ((NMAX + SCAN_TB - 1) / SCAN_TB)

__device__ __align__(16) float   g_agg[NMAX * 32];  // layer-2 aggregated means (fp32)
__device__ __align__(16) __half2 g_xh[NPAD * 32];   // x in fp16 (64 per node)
__device__ __align__(16) __half2 g_mh[NPAD * 32];   // layer-1 mean in fp16 (64 per node)
__device__ __align__(16) __half2 g_p2[NPAD * 16];   // h1@W2l in fp16 (32 per node)
__device__ __align__(16) float   g_r2[NMAX * 32];   // h1@W2r in fp32 (self term)
__device__ __half g_W1lh[64 * 64];
__device__ __half g_W1rh[64 * 64];
__device__ __half g_W2lh[64 * 32];
__device__ __half g_W2rh[64 * 32];
__device__ float g_p3[NMAX];                        // h2 @ W3l
__device__ float g_r3[NMAX];                        // h2 @ W3r (self term)
__device__ float g_inv[NMAX];                       // 1 / max(deg, 1)
__device__ int   g_deg[NMAX];
__device__ int   g_start[NMAX];
__device__ int   g_fill[NMAX];
__device__ int   g_bsum[NBLK + 1];
__device__ int   g_csr[EMAX];                       // src ids bucketed by dst

// ---------------- CSR build ----------------

__global__ void zero_deg_kernel(int N) {
    int i = blockIdx.x * blockDim.x + threadIdx.x;
    if (i < N) g_deg[i] = 0;
}

__global__ void hist_kernel(const int* __restrict__ dst, int E) {
    int e = blockIdx.x * blockDim.x + threadIdx.x;
    if (e < E) atomicAdd(&g_deg[dst[e]], 1);
}

__global__ void blocksum_kernel(int N) {
    __shared__ int sred[SCAN_TB];
    int i = blockIdx.x * SCAN_TB + threadIdx.x;
    int d = (i < N) ? g_deg[i] : 0;
    sred[threadIdx.x] = d;
    __syncthreads();
    for (int off = SCAN_TB / 2; off > 0; off >>= 1) {
        if (threadIdx.x < off) sred[threadIdx.x] += sred[threadIdx.x + off];
        __syncthreads();
    }
    if (threadIdx.x == 0) g_bsum[blockIdx.x] = sred[0];
}

__global__ void scan_bsums_kernel(int nb) {
    if (threadIdx.x == 0) {
        int acc = 0;
        for (int i = 0; i < nb; i++) {
            int v = g_bsum[i];
            g_bsum[i] = acc;
            acc += v;
        }
    }
}

__global__ void starts_kernel(int N) {
    __shared__ int stmp[SCAN_TB];
    int i = blockIdx.x * SCAN_TB + threadIdx.x;
    int d = (i < N) ? g_deg[i] : 0;
    stmp[threadIdx.x] = d;
    __syncthreads();
    for (int off = 1; off < SCAN_TB; off <<= 1) {
        int v = (threadIdx.x >= off) ? stmp[threadIdx.x - off] : 0;
        __syncthreads();
        stmp[threadIdx.x] += v;
        __syncthreads();
    }
    if (i < N) {
        int excl = stmp[threadIdx.x] - d + g_bsum[blockIdx.x];
        g_start[i] = excl;
        g_inv[i] = 1.0f / fmaxf((float)d, 1.0f);
        g_fill[i] = 0;
    }
}

__global__ void place_kernel(const int* __restrict__ src,
                             const int* __restrict__ dst, int E) {
    int e = blockIdx.x * blockDim.x + threadIdx.x;
    if (e >= E) return;
    int d = dst[e];
    int pos = g_start[d] + atomicAdd(&g_fill[d], 1);
    g_csr[pos] = src[e];
}

// ---------------- fp16 conversions ----------------

__global__ void convert_x_kernel(const float* __restrict__ x, int N) {
    int t = blockIdx.x * blockDim.x + threadIdx.x;
    if (t >= N * 32) return;
    float2 v = ((const float2*)x)[t];
    g_xh[t] = __floats2half2_rn(v.x, v.y);
}

__global__ void convert_w_kernel(const float* __restrict__ W1l,
                                 const float* __restrict__ W1r,
                                 const float* __restrict__ W2l,
                                 const float* __restrict__ W2r) {
    int t = blockIdx.x * blockDim.x + threadIdx.x;
    if (t < 4096) g_W1lh[t] = __float2half_rn(W1l[t]);
    else if (t < 8192) g_W1rh[t - 4096] = __float2half_rn(W1r[t - 4096]);
    else if (t < 10240) g_W2lh[t - 8192] = __float2half_rn(W2l[t - 8192]);
    else if (t < 12288) g_W2rh[t - 10240] = __float2half_rn(W2r[t - 10240]);
}

// ---------------- gathers (mean, fp16 sources, fp32 accumulate) ----------------

// 64-d: one warp per node, lane owns one half2. Emits mean in fp16 (g_mh).
__global__ void gather64h_kernel(int N) {
    int g = blockIdx.x * blockDim.x + threadIdx.x;
    int node = g >> 5;
    int lane = g & 31;
    if (node >= N) return;
    int s0 = g_start[node];
    int d = g_deg[node];
    float ax = 0.f, ay = 0.f;
    int j = 0;
    for (; j + 8 <= d; j += 8) {
        int si[8];
#pragma unroll
        for (int u = 0; u < 8; u++) si[u] = g_csr[s0 + j + u];
        __half2 v[8];
#pragma unroll
        for (int u = 0; u < 8; u++) v[u] = g_xh[si[u] * 32 + lane];
#pragma unroll
        for (int u = 0; u < 8; u++) {
            float2 f = __half22float2(v[u]);
            ax += f.x;
            ay += f.y;
        }
    }
    for (; j < d; j++) {
        float2 f = __half22float2(g_xh[g_csr[s0 + j] * 32 + lane]);
        ax += f.x;
        ay += f.y;
    }
    float iv = g_inv[node];
    g_mh[node * 32 + lane] = __floats2half2_rn(ax * iv, ay * iv);
}

// 32-d: two nodes per warp, 16 lanes per node, lane owns one half2.
__global__ void gather32h_kernel(int N) {
    int g = blockIdx.x * blockDim.x + threadIdx.x;
    int node = g >> 4;
    int lane = g & 15;
    if (node >= N) return;
    int s0 = g_start[node];
    int d = g_deg[node];
    float ax = 0.f, ay = 0.f;
    int j = 0;
    for (; j + 8 <= d; j += 8) {
        int si[8];
#pragma unroll
        for (int u = 0; u < 8; u++) si[u] = g_csr[s0 + j + u];
        __half2 v[8];
#pragma unroll
        for (int u = 0; u < 8; u++) v[u] = g_p2[si[u] * 16 + lane];
#pragma unroll
        for (int u = 0; u < 8; u++) {
            float2 f = __half22float2(v[u]);
            ax += f.x;
            ay += f.y;
        }
    }
    for (; j < d; j++) {
        float2 f = __half22float2(g_p2[g_csr[s0 + j] * 16 + lane]);
        ax += f.x;
        ay += f.y;
    }
    float iv = g_inv[node];
    ((float2*)g_agg)[node * 16 + lane] = make_float2(ax * iv, ay * iv);
}

// ---------------- tensor-core fused dense chain ----------------
// Per block: 64 nodes, 128 threads (4 warps). Phase A: H1 = relu(mean@W1l +
// x@W1r + b1) via wmma (fp16 in, fp32 acc) -> smem fp16. Phase B: P2 = H1@W2l
// (fp16 out), R2 = H1@W2r (fp32 out) via wmma from smem H1.
__global__ void dense_wmma_kernel(const float* __restrict__ b1, int N) {
    __shared__ float  sF[64 * 64];   // fp32 staging (16KB)
    __shared__ __half sH[64 * 64];   // H1 fp16 (8KB)
    int warp = threadIdx.x >> 5;
    int base = blockIdx.x * 64;
    const __half* mh = (const __half*)g_mh;
    const __half* xh = (const __half*)g_xh;

    wmma::fragment<wmma::accumulator, 16, 16, 16, float> acc;
    wmma::fragment<wmma::matrix_a, 16, 16, 16, __half, wmma::row_major> fa;
    wmma::fragment<wmma::matrix_b, 16, 16, 16, __half, wmma::row_major> fb;

    // Phase A: each warp computes rows [16*warp, 16*warp+16) x all 64 cols.
    int arow = (base + warp * 16) * 64;
#pragma unroll
    for (int nt = 0; nt < 4; nt++) {
        wmma::fill_fragment(acc, 0.f);
#pragma unroll
        for (int k = 0; k < 4; k++) {
            wmma::load_matrix_sync(fa, mh + arow + k * 16, 64);
            wmma::load_matrix_sync(fb, g_W1lh + (k * 16) * 64 + nt * 16, 64);
            wmma::mma_sync(acc, fa, fb, acc);
            wmma::load_matrix_sync(fa, xh + arow + k * 16, 64);
            wmma::load_matrix_sync(fb, g_W1rh + (k * 16) * 64 + nt * 16, 64);
            wmma::mma_sync(acc, fa, fb, acc);
        }
        wmma::store_matrix_sync(sF + (warp * 16) * 64 + nt * 16, acc, 64, wmma::mem_row_major);
    }
    __syncthreads();
    for (int i = threadIdx.x; i < 64 * 64; i += blockDim.x) {
        int col = i & 63;
        sH[i] = __float2half_rn(fmaxf(sF[i] + b1[col], 0.f));
    }
    __syncthreads();

    // Phase B1: P2 = H1 @ W2l (64x32), fp16 out.
#pragma unroll
    for (int nt = 0; nt < 2; nt++) {
        wmma::fill_fragment(acc, 0.f);
#pragma unroll
        for (int k = 0; k < 4; k++) {
            wmma::load_matrix_sync(fa, sH + (warp * 16) * 64 + k * 16, 64);
            wmma::load_matrix_sync(fb, g_W2lh + (k * 16) * 32 + nt * 16, 32);
            wmma::mma_sync(acc, fa, fb, acc);
        }
        wmma::store_matrix_sync(sF + (warp * 16) * 32 + nt * 16, acc, 32, wmma::mem_row_major);
    }
    __syncthreads();
    for (int i = threadIdx.x; i < 64 * 32; i += blockDim.x) {
        int node = base + (i >> 5);
        if (node < N) ((__half*)g_p2)[node * 32 + (i & 31)] = __float2half_rn(sF[i]);
    }
    __syncthreads();

    // Phase B2: R2 = H1 @ W2r (64x32), fp32 out.
#pragma unroll
    for (int nt = 0; nt < 2; nt++) {
        wmma::fill_fragment(acc, 0.f);
#pragma unroll
        for (int k = 0; k < 4; k++) {
            wmma::load_matrix_sync(fa, sH + (warp * 16) * 64 + k * 16, 64);
            wmma::load_matrix_sync(fb, g_W2rh + (k * 16) * 32 + nt * 16, 32);
            wmma::mma_sync(acc, fa, fb, acc);
        }
        wmma::store_matrix_sync(sF + (warp * 16) * 32 + nt * 16, acc, 32, wmma::mem_row_major);
    }
    __syncthreads();
    for (int i = threadIdx.x; i < 64 * 32; i += blockDim.x) {
        int node = base + (i >> 5);
        if (node < N) g_r2[node * 32 + (i & 31)] = sF[i];
    }
}

// Layer-2 combine (elementwise) + both layer-3 dots. One warp per node.
__global__ void combine2_small_kernel(const float* __restrict__ b2,
                                      const float* __restrict__ W3l,
                                      const float* __restrict__ W3r, int N) {
    __shared__ float sb[32], s3l[32], s3r[32];
    if (threadIdx.x < 32) {
        sb[threadIdx.x] = b2[threadIdx.x];
        s3l[threadIdx.x] = W3l[threadIdx.x];
        s3r[threadIdx.x] = W3r[threadIdx.x];
    }
    __syncthreads();
    int g = blockIdx.x * blockDim.x + threadIdx.x;
    int node = g >> 5;
    int lane = g & 31;
    if (node >= N) return;
    float h2 = fmaxf(g_agg[node * 32 + lane] + sb[lane] + g_r2[node * 32 + lane], 0.f);
    float a = h2 * s3l[lane];
    float r = h2 * s3r[lane];
#pragma unroll
    for (int off = 16; off; off >>= 1) {
        a += __shfl_xor_sync(0xffffffffu, a, off);
        r += __shfl_xor_sync(0xffffffffu, r, off);
    }
    if (lane == 0) {
        g_p3[node] = a;
        g_r3[node] = r;
    }
}

// Final: one warp per node, lanes parallel over edges; fused sigmoid.
__global__ void gather1_final_kernel(const float* __restrict__ b3,
                                     float* __restrict__ out, int N) {
    int g = blockIdx.x * blockDim.x + threadIdx.x;
    int node = g >> 5;
    int lane = g & 31;
    if (node >= N) return;
    int s0 = g_start[node];
    int d = g_deg[node];
    float acc = 0.f;
    for (int j = lane; j < d; j += 32) acc += g_p3[g_csr[s0 + j]];
#pragma unroll
    for (int off = 16; off; off >>= 1) acc += __shfl_xor_sync(0xffffffffu, acc, off);
    if (lane == 0) {
        float v = acc * g_inv[node] + b3[0] + g_r3[node];
        out[node] = 1.0f / (1.0f + expf(-v));
    }
}

// ---------------- launch ----------------

extern "C" void kernel_launch(void* const* d_in, const int* in_sizes, int n_in,
                              void* d_out, int out_size) {
    const float* x   = (const float*)d_in[0];
    const int*   ei  = (const int*)d_in[1];   // int32 (JAX x64 disabled)
    const float* W1l = (const float*)d_in[2];
    const float* b1  = (const float*)d_in[3];
    const float* W1r = (const float*)d_in[4];
    const float* W2l = (const float*)d_in[5];
    const float* b2  = (const float*)d_in[6];
    const float* W2r = (const float*)d_in[7];
    const float* W3l = (const float*)d_in[8];
    const float* b3  = (const float*)d_in[9];
    const float* W3r = (const float*)d_in[10];
    float* out = (float*)d_out;

    int N = in_sizes[0] / 64;
    int E = in_sizes[1] / 2;
    const int* src = ei;
    const int* dst = ei + E;

    const int TB = 256;
    auto blocks = [](long long n, int tb) { return (int)((n + tb - 1) / tb); };
    int nb = (N + SCAN_TB - 1) / SCAN_TB;

    // CSR build; fp16 conversions interleaved.
    zero_deg_kernel<<<blocks(N, TB), TB>>>(N);
    hist_kernel<<<blocks(E, TB), TB>>>(dst, E);
    convert_x_kernel<<<blocks((long long)N * 32, TB), TB>>>(x, N);
    convert_w_kernel<<<48, 256>>>(W1l, W1r, W2l, W2r);
    blocksum_kernel<<<nb, SCAN_TB>>>(N);
    scan_bsums_kernel<<<1, 32>>>(nb);
    starts_kernel<<<nb, SCAN_TB>>>(N);
    place_kernel<<<blocks(E, TB), TB>>>(src, dst, E);

    // ---- layer 1: gather x (fp16) -> fp16 mean; wmma dense chain ----
    gather64h_kernel<<<blocks((long long)N * 32, TB), TB>>>(N);
    dense_wmma_kernel<<<(N + 63) / 64, 128>>>(b1, N);

    // ---- layer 2: gather p2, elementwise combine + layer-3 dots ----
    gather32h_kernel<<<blocks((long long)N * 16, TB), TB>>>(N);
    combine2_small_kernel<<<blocks((long long)N * 32, TB), TB>>>(b2, W3l, W3r, N);

    // ---- layer 3: scalar gather + sigmoid ----
    gather1_final_kernel<<<blocks((long long)N * 32, TB), TB>>>(b3, out, N);
}

// round 12
// speedup vs baseline: 2.1548x; 1.0557x over previous
#include <cuda_runtime.h>
#include <cuda_fp16.h>
#include <mma.h>
#include <math.h>

using namespace nvcuda;

// GraphSAGE 3-layer, N=100000, E=3200000, D: 64 -> 64 -> 32 -> 1
// CSR-gather aggregation (fp16, wide LDG.128 lanes) + wmma fused dense chain.

#define NMAX 100000
#define NPAD 100096   // padded to 64-node tiles for wmma
#define EMAX 3200000
#define SCAN_TB 1024
#define NBLK ((NMAX + SCAN_TB - 1) / SCAN_TB)   // 98 <= 128

__device__ __align__(16) float   g_agg[NMAX * 32];  // layer-2 aggregated means (fp32)
__device__ __align__(16) __half2 g_xh[NPAD * 32];   // x in fp16 (64 per node)
__device__ __align__(16) __half2 g_mh[NPAD * 32];   // layer-1 mean in fp16
__device__ __align__(16) __half2 g_p2[NPAD * 16];   // h1@W2l in fp16 (32 per node)
__device__ __align__(16) float   g_r2[NMAX * 32];   // h1@W2r in fp32 (self term)
__device__ __half g_W1lh[64 * 64];
__device__ __half g_W1rh[64 * 64];
__device__ __half g_W2lh[64 * 32];
__device__ __half g_W2rh[64 * 32];
__device__ float g_p3[NMAX];
__device__ float g_r3[NMAX];
__device__ float g_inv[NMAX];
__device__ int   g_deg[NMAX];
__device__ int   g_start[NMAX];
__device__ int   g_fill[NMAX];
__device__ int   g_bsum[128];
__device__ int   g_csr[EMAX];

// ---------------- CSR build ----------------

__global__ void zero_deg_kernel(int N) {
    int i = blockIdx.x * blockDim.x + threadIdx.x;
    if (i < N) g_deg[i] = 0;
}

// 4 edges per thread, int4 loads.
__global__ void hist_kernel(const int* __restrict__ dst, int E) {
    int t = blockIdx.x * blockDim.x + threadIdx.x;
    int e = t * 4;
    if (e + 4 <= E) {
        int4 d = *(const int4*)(dst + e);
        atomicAdd(&g_deg[d.x], 1);
        atomicAdd(&g_deg[d.y], 1);
        atomicAdd(&g_deg[d.z], 1);
        atomicAdd(&g_deg[d.w], 1);
    } else {
        for (int i = e; i < E; i++) atomicAdd(&g_deg[dst[i]], 1);
    }
}

__global__ void blocksum_kernel(int N) {
    __shared__ int sred[SCAN_TB];
    int i = blockIdx.x * SCAN_TB + threadIdx.x;
    int d = (i < N) ? g_deg[i] : 0;
    sred[threadIdx.x] = d;
    __syncthreads();
    for (int off = SCAN_TB / 2; off > 0; off >>= 1) {
        if (threadIdx.x < off) sred[threadIdx.x] += sred[threadIdx.x + off];
        __syncthreads();
    }
    if (threadIdx.x == 0) g_bsum[blockIdx.x] = sred[0];
}

// Parallel exclusive scan of <=128 block sums (one block of 128 threads).
__global__ void scan_bsums_kernel(int nb) {
    __shared__ int s[128];
    int v = (threadIdx.x < nb) ? g_bsum[threadIdx.x] : 0;
    s[threadIdx.x] = v;
    __syncthreads();
    for (int off = 1; off < 128; off <<= 1) {
        int t = (threadIdx.x >= off) ? s[threadIdx.x - off] : 0;
        __syncthreads();
        s[threadIdx.x] += t;
        __syncthreads();
    }
    if (threadIdx.x < nb) g_bsum[threadIdx.x] = s[threadIdx.x] - v;
}

__global__ void starts_kernel(int N) {
    __shared__ int stmp[SCAN_TB];
    int i = blockIdx.x * SCAN_TB + threadIdx.x;
    int d = (i < N) ? g_deg[i] : 0;
    stmp[threadIdx.x] = d;
    __syncthreads();
    for (int off = 1; off < SCAN_TB; off <<= 1) {
        int v = (threadIdx.x >= off) ? stmp[threadIdx.x - off] : 0;
        __syncthreads();
        stmp[threadIdx.x] += v;
        __syncthreads();
    }
    if (i < N) {
        int excl = stmp[threadIdx.x] - d + g_bsum[blockIdx.x];
        g_start[i] = excl;
        g_inv[i] = 1.0f / fmaxf((float)d, 1.0f);
        g_fill[i] = 0;
    }
}

// 4 edges per thread, int4 loads of src and dst.
__global__ void place_kernel(const int* __restrict__ src,
                             const int* __restrict__ dst, int E) {
    int t = blockIdx.x * blockDim.x + threadIdx.x;
    int e = t * 4;
    if (e + 4 <= E) {
        int4 d = *(const int4*)(dst + e);
        int4 s = *(const int4*)(src + e);
        g_csr[g_start[d.x] + atomicAdd(&g_fill[d.x], 1)] = s.x;
        g_csr[g_start[d.y] + atomicAdd(&g_fill[d.y], 1)] = s.y;
        g_csr[g_start[d.z] + atomicAdd(&g_fill[d.z], 1)] = s.z;
        g_csr[g_start[d.w] + atomicAdd(&g_fill[d.w], 1)] = s.w;
    } else {
        for (int i = e; i < E; i++)
            g_csr[g_start[dst[i]] + atomicAdd(&g_fill[dst[i]], 1)] = src[i];
    }
}

// ---------------- fp16 conversions (x + weights merged) ----------------

__global__ void convert_kernel(const float* __restrict__ x,
                               const float* __restrict__ W1l,
                               const float* __restrict__ W1r,
                               const float* __restrict__ W2l,
                               const float* __restrict__ W2r, int N) {
    int t = blockIdx.x * blockDim.x + threadIdx.x;
    if (t < N * 32) {
        float2 v = ((const float2*)x)[t];
        g_xh[t] = __floats2half2_rn(v.x, v.y);
    }
    if (t < 4096) g_W1lh[t] = __float2half_rn(W1l[t]);
    else if (t < 8192) g_W1rh[t - 4096] = __float2half_rn(W1r[t - 4096]);
    else if (t < 10240) g_W2lh[t - 8192] = __float2half_rn(W2l[t - 8192]);
    else if (t < 12288) g_W2rh[t - 10240] = __float2half_rn(W2r[t - 10240]);
}

// ---------------- gathers (mean, fp16 sources, wide lanes) ----------------

// 64-d: 4 nodes per warp, 8 lanes per node, each lane one int4 (16B) of the
// 128B row. One row LDG.128 warp-instr covers 4 edge-rows.
__global__ void gather64_v4_kernel(int N) {
    int g = blockIdx.x * blockDim.x + threadIdx.x;
    int warp = g >> 5;
    int lane = g & 31;
    int node = warp * 4 + (lane >> 3);
    int lg = lane & 7;
    if (node >= N) return;
    int s0 = g_start[node];
    int d = g_deg[node];
    const int4* xrow = (const int4*)g_xh;   // 8 int4 per 64-dim row
    float a0 = 0.f, a1 = 0.f, a2 = 0.f, a3 = 0.f;
    float a4 = 0.f, a5 = 0.f, a6 = 0.f, a7 = 0.f;
    int j = 0;
    for (; j + 4 <= d; j += 4) {
        int si[4];
#pragma unroll
        for (int u = 0; u < 4; u++) si[u] = g_csr[s0 + j + u];
        int4 v[4];
#pragma unroll
        for (int u = 0; u < 4; u++) v[u] = xrow[si[u] * 8 + lg];
#pragma unroll
        for (int u = 0; u < 4; u++) {
            float2 f0 = __half22float2(*(__half2*)&v[u].x);
            float2 f1 = __half22float2(*(__half2*)&v[u].y);
            float2 f2 = __half22float2(*(__half2*)&v[u].z);
            float2 f3 = __half22float2(*(__half2*)&v[u].w);
            a0 += f0.x; a1 += f0.y; a2 += f1.x; a3 += f1.y;
            a4 += f2.x; a5 += f2.y; a6 += f3.x; a7 += f3.y;
        }
    }
    for (; j < d; j++) {
        int4 v = xrow[g_csr[s0 + j] * 8 + lg];
        float2 f0 = __half22float2(*(__half2*)&v.x);
        float2 f1 = __half22float2(*(__half2*)&v.y);
        float2 f2 = __half22float2(*(__half2*)&v.z);
        float2 f3 = __half22float2(*(__half2*)&v.w);
        a0 += f0.x; a1 += f0.y; a2 += f1.x; a3 += f1.y;
        a4 += f2.x; a5 += f2.y; a6 += f3.x; a7 += f3.y;
    }
    float iv = g_inv[node];
    __half2 o0 = __floats2half2_rn(a0 * iv, a1 * iv);
    __half2 o1 = __floats2half2_rn(a2 * iv, a3 * iv);
    __half2 o2 = __floats2half2_rn(a4 * iv, a5 * iv);
    __half2 o3 = __floats2half2_rn(a6 * iv, a7 * iv);
    int4 ov;
    ov.x = *(int*)&o0; ov.y = *(int*)&o1; ov.z = *(int*)&o2; ov.w = *(int*)&o3;
    ((int4*)g_mh)[node * 8 + lg] = ov;
}

// 32-d: 8 nodes per warp, 4 lanes per node, each lane one int4 (16B) of the
// 64B row. Output is fp32 g_agg (128B row; lane writes two float4).
__global__ void gather32_v8_kernel(int N) {
    int g = blockIdx.x * blockDim.x + threadIdx.x;
    int warp = g >> 5;
    int lane = g & 31;
    int node = warp * 8 + (lane >> 2);
    int lg = lane & 3;
    if (node >= N) return;
    int s0 = g_start[node];
    int d = g_deg[node];
    const int4* prow = (const int4*)g_p2;   // 4 int4 per 32-dim row
    float a0 = 0.f, a1 = 0.f, a2 = 0.f, a3 = 0.f;
    float a4 = 0.f, a5 = 0.f, a6 = 0.f, a7 = 0.f;
    int j = 0;
    for (; j + 4 <= d; j += 4) {
        int si[4];
#pragma unroll
        for (int u = 0; u < 4; u++) si[u] = g_csr[s0 + j + u];
        int4 v[4];
#pragma unroll
        for (int u = 0; u < 4; u++) v[u] = prow[si[u] * 4 + lg];
#pragma unroll
        for (int u = 0; u < 4; u++) {
            float2 f0 = __half22float2(*(__half2*)&v[u].x);
            float2 f1 = __half22float2(*(__half2*)&v[u].y);
            float2 f2 = __half22float2(*(__half2*)&v[u].z);
            float2 f3 = __half22float2(*(__half2*)&v[u].w);
            a0 += f0.x; a1 += f0.y; a2 += f1.x; a3 += f1.y;
            a4 += f2.x; a5 += f2.y; a6 += f3.x; a7 += f3.y;
        }
    }
    for (; j < d; j++) {
        int4 v = prow[g_csr[s0 + j] * 4 + lg];
        float2 f0 = __half22float2(*(__half2*)&v.x);
        float2 f1 = __half22float2(*(__half2*)&v.y);
        float2 f2 = __half22float2(*(__half2*)&v.z);
        float2 f3 = __half22float2(*(__half2*)&v.w);
        a0 += f0.x; a1 += f0.y; a2 += f1.x; a3 += f1.y;
        a4 += f2.x; a5 += f2.y; a6 += f3.x; a7 += f3.y;
    }
    float iv = g_inv[node];
    float4* outp = (float4*)(g_agg + node * 32 + lg * 8);
    outp[0] = make_float4(a0 * iv, a1 * iv, a2 * iv, a3 * iv);
    outp[1] = make_float4(a4 * iv, a5 * iv, a6 * iv, a7 * iv);
}

// ---------------- tensor-core fused dense chain ----------------

__global__ void dense_wmma_kernel(const float* __restrict__ b1, int N) {
    __shared__ float  sF[64 * 64];
    __shared__ __half sH[64 * 64];
    int warp = threadIdx.x >> 5;
    int base = blockIdx.x * 64;
    const __half* mh = (const __half*)g_mh;
    const __half* xh = (const __half*)g_xh;

    wmma::fragment<wmma::accumulator, 16, 16, 16, float> acc;
    wmma::fragment<wmma::matrix_a, 16, 16, 16, __half, wmma::row_major> fa;
    wmma::fragment<wmma::matrix_b, 16, 16, 16, __half, wmma::row_major> fb;

    int arow = (base + warp * 16) * 64;
#pragma unroll
    for (int nt = 0; nt < 4; nt++) {
        wmma::fill_fragment(acc, 0.f);
#pragma unroll
        for (int k = 0; k < 4; k++) {
            wmma::load_matrix_sync(fa, mh + arow + k * 16, 64);
            wmma::load_matrix_sync(fb, g_W1lh + (k * 16) * 64 + nt * 16, 64);
            wmma::mma_sync(acc, fa, fb, acc);
            wmma::load_matrix_sync(fa, xh + arow + k * 16, 64);
            wmma::load_matrix_sync(fb, g_W1rh + (k * 16) * 64 + nt * 16, 64);
            wmma::mma_sync(acc, fa, fb, acc);
        }
        wmma::store_matrix_sync(sF + (warp * 16) * 64 + nt * 16, acc, 64, wmma::mem_row_major);
    }
    __syncthreads();
    for (int i = threadIdx.x; i < 64 * 64; i += blockDim.x) {
        int col = i & 63;
        sH[i] = __float2half_rn(fmaxf(sF[i] + b1[col], 0.f));
    }
    __syncthreads();

#pragma unroll
    for (int nt = 0; nt < 2; nt++) {
        wmma::fill_fragment(acc, 0.f);
#pragma unroll
        for (int k = 0; k < 4; k++) {
            wmma::load_matrix_sync(fa, sH + (warp * 16) * 64 + k * 16, 64);
            wmma::load_matrix_sync(fb, g_W2lh + (k * 16) * 32 + nt * 16, 32);
            wmma::mma_sync(acc, fa, fb, acc);
        }
        wmma::store_matrix_sync(sF + (warp * 16) * 32 + nt * 16, acc, 32, wmma::mem_row_major);
    }
    __syncthreads();
    for (int i = threadIdx.x; i < 64 * 32; i += blockDim.x) {
        int node = base + (i >> 5);
        if (node < N) ((__half*)g_p2)[node * 32 + (i & 31)] = __float2half_rn(sF[i]);
    }
    __syncthreads();

#pragma unroll
    for (int nt = 0; nt < 2; nt++) {
        wmma::fill_fragment(acc, 0.f);
#pragma unroll
        for (int k = 0; k < 4; k++) {
            wmma::load_matrix_sync(fa, sH + (warp * 16) * 64 + k * 16, 64);
            wmma::load_matrix_sync(fb, g_W2rh + (k * 16) * 32 + nt * 16, 32);
            wmma::mma_sync(acc, fa, fb, acc);
        }
        wmma::store_matrix_sync(sF + (warp * 16) * 32 + nt * 16, acc, 32, wmma::mem_row_major);
    }
    __syncthreads();
    for (int i = threadIdx.x; i < 64 * 32; i += blockDim.x) {
        int node = base + (i >> 5);
        if (node < N) g_r2[node * 32 + (i & 31)] = sF[i];
    }
}

// Layer-2 combine (elementwise) + both layer-3 dots. One warp per node.
__global__ void combine2_small_kernel(const float* __restrict__ b2,
                                      const float* __restrict__ W3l,
                                      const float* __restrict__ W3r, int N) {
    __shared__ float sb[32], s3l[32], s3r[32];
    if (threadIdx.x < 32) {
        sb[threadIdx.x] = b2[threadIdx.x];
        s3l[threadIdx.x] = W3l[threadIdx.x];
        s3r[threadIdx.x] = W3r[threadIdx.x];
    }
    __syncthreads();
    int g = blockIdx.x * blockDim.x + threadIdx.x;
    int node = g >> 5;
    int lane = g & 31;
    if (node >= N) return;
    float h2 = fmaxf(g_agg[node * 32 + lane] + sb[lane] + g_r2[node * 32 + lane], 0.f);
    float a = h2 * s3l[lane];
    float r = h2 * s3r[lane];
#pragma unroll
    for (int off = 16; off; off >>= 1) {
        a += __shfl_xor_sync(0xffffffffu, a, off);
        r += __shfl_xor_sync(0xffffffffu, r, off);
    }
    if (lane == 0) {
        g_p3[node] = a;
        g_r3[node] = r;
    }
}

__global__ void gather1_final_kernel(const float* __restrict__ b3,
                                     float* __restrict__ out, int N) {
    int g = blockIdx.x * blockDim.x + threadIdx.x;
    int node = g >> 5;
    int lane = g & 31;
    if (node >= N) return;
    int s0 = g_start[node];
    int d = g_deg[node];
    float acc = 0.f;
    for (int j = lane; j < d; j += 32) acc += g_p3[g_csr[s0 + j]];
#pragma unroll
    for (int off = 16; off; off >>= 1) acc += __shfl_xor_sync(0xffffffffu, acc, off);
    if (lane == 0) {
        float v = acc * g_inv[node] + b3[0] + g_r3[node];
        out[node] = 1.0f / (1.0f + expf(-v));
    }
}

// ---------------- launch ----------------

extern "C" void kernel_launch(void* const* d_in, const int* in_sizes, int n_in,
                              void* d_out, int out_size) {
    const float* x   = (const float*)d_in[0];
    const int*   ei  = (const int*)d_in[1];   // int32 (JAX x64 disabled)
    const float* W1l = (const float*)d_in[2];
    const float* b1  = (const float*)d_in[3];
    const float* W1r = (const float*)d_in[4];
    const float* W2l = (const float*)d_in[5];
    const float* b2  = (const float*)d_in[6];
    const float* W2r = (const float*)d_in[7];
    const float* W3l = (const float*)d_in[8];
    const float* b3  = (const float*)d_in[9];
    const float* W3r = (const float*)d_in[10];
    float* out = (float*)d_out;

    int N = in_sizes[0] / 64;
    int E = in_sizes[1] / 2;
    const int* src = ei;
    const int* dst = ei + E;

    const int TB = 256;
    auto blocks = [](long long n, int tb) { return (int)((n + tb - 1) / tb); };
    int nb = (N + SCAN_TB - 1) / SCAN_TB;
    int E4 = (E + 3) / 4;

    zero_deg_kernel<<<blocks(N, TB), TB>>>(N);
    hist_kernel<<<blocks(E4, TB), TB>>>(dst, E);
    convert_kernel<<<blocks((long long)N * 32, TB), TB>>>(x, W1l, W1r, W2l, W2r, N);
    blocksum_kernel<<<nb, SCAN_TB>>>(N);
    scan_bsums_kernel<<<1, 128>>>(nb);
    starts_kernel<<<nb, SCAN_TB>>>(N);
    place_kernel<<<blocks(E4, TB), TB>>>(src, dst, E);

    // ---- layer 1: wide gather -> fp16 mean; wmma dense chain ----
    gather64_v4_kernel<<<blocks((long long)N * 8, TB), TB>>>(N);
    dense_wmma_kernel<<<(N + 63) / 64, 128>>>(b1, N);

    // ---- layer 2: wide gather p2, elementwise combine + layer-3 dots ----
    gather32_v8_kernel<<<blocks((long long)N * 4, TB), TB>>>(N);
    combine2_small_kernel<<<blocks((long long)N * 32, TB), TB>>>(b2, W3l, W3r, N);

    // ---- layer 3: scalar gather + sigmoid ----
    gather1_final_kernel<<<blocks((long long)N * 32, TB), TB>>>(b3, out, N);
}

// round 13
// speedup vs baseline: 2.2414x; 1.0402x over previous
#include <cuda_runtime.h>
#include <cuda_fp16.h>
#include <mma.h>
#include <math.h>

using namespace nvcuda;

// GraphSAGE 3-layer, N=100000, E=3200000, D: 64 -> 64 -> 32 -> 1
// CSR gather (fp16 wide lanes) + wmma dense chain.
// R13: combine2 fused into gather32 epilogue (g_agg eliminated);
// zero_deg folded into convert; hist/place 8 edges/thread.

#define NMAX 100000
#define NPAD 100096
#define EMAX 3200000
#define SCAN_TB 1024
#define NBLK ((NMAX + SCAN_TB - 1) / SCAN_TB)

__device__ __align__(16) __half2 g_xh[NPAD * 32];   // x in fp16 (64 per node)
__device__ __align__(16) __half2 g_mh[NPAD * 32];   // layer-1 mean in fp16
__device__ __align__(16) __half2 g_p2[NPAD * 16];   // h1@W2l in fp16 (32 per node)
__device__ __align__(16) float   g_r2[NMAX * 32];   // h1@W2r in fp32 (self term)
__device__ __half g_W1lh[64 * 64];
__device__ __half g_W1rh[64 * 64];
__device__ __half g_W2lh[64 * 32];
__device__ __half g_W2rh[64 * 32];
__device__ float g_p3[NMAX];
__device__ float g_r3[NMAX];
__device__ float g_inv[NMAX];
__device__ int   g_deg[NMAX];
__device__ int   g_start[NMAX];
__device__ int   g_fill[NMAX];
__device__ int   g_bsum[128];
__device__ int   g_csr[EMAX];

// ---------------- CSR build ----------------

// 8 edges per thread, two int4 loads.
__global__ void hist_kernel(const int* __restrict__ dst, int E) {
    int t = blockIdx.x * blockDim.x + threadIdx.x;
    int e = t * 8;
    if (e + 8 <= E) {
        int4 d0 = *(const int4*)(dst + e);
        int4 d1 = *(const int4*)(dst + e + 4);
        atomicAdd(&g_deg[d0.x], 1);
        atomicAdd(&g_deg[d0.y], 1);
        atomicAdd(&g_deg[d0.z], 1);
        atomicAdd(&g_deg[d0.w], 1);
        atomicAdd(&g_deg[d1.x], 1);
        atomicAdd(&g_deg[d1.y], 1);
        atomicAdd(&g_deg[d1.z], 1);
        atomicAdd(&g_deg[d1.w], 1);
    } else {
        for (int i = e; i < E; i++) atomicAdd(&g_deg[dst[i]], 1);
    }
}

__global__ void blocksum_kernel(int N) {
    __shared__ int sred[SCAN_TB];
    int i = blockIdx.x * SCAN_TB + threadIdx.x;
    int d = (i < N) ? g_deg[i] : 0;
    sred[threadIdx.x] = d;
    __syncthreads();
    for (int off = SCAN_TB / 2; off > 0; off >>= 1) {
        if (threadIdx.x < off) sred[threadIdx.x] += sred[threadIdx.x + off];
        __syncthreads();
    }
    if (threadIdx.x == 0) g_bsum[blockIdx.x] = sred[0];
}

__global__ void scan_bsums_kernel(int nb) {
    __shared__ int s[128];
    int v = (threadIdx.x < nb) ? g_bsum[threadIdx.x] : 0;
    s[threadIdx.x] = v;
    __syncthreads();
    for (int off = 1; off < 128; off <<= 1) {
        int t = (threadIdx.x >= off) ? s[threadIdx.x - off] : 0;
        __syncthreads();
        s[threadIdx.x] += t;
        __syncthreads();
    }
    if (threadIdx.x < nb) g_bsum[threadIdx.x] = s[threadIdx.x] - v;
}

__global__ void starts_kernel(int N) {
    __shared__ int stmp[SCAN_TB];
    int i = blockIdx.x * SCAN_TB + threadIdx.x;
    int d = (i < N) ? g_deg[i] : 0;
    stmp[threadIdx.x] = d;
    __syncthreads();
    for (int off = 1; off < SCAN_TB; off <<= 1) {
        int v = (threadIdx.x >= off) ? stmp[threadIdx.x - off] : 0;
        __syncthreads();
        stmp[threadIdx.x] += v;
        __syncthreads();
    }
    if (i < N) {
        int excl = stmp[threadIdx.x] - d + g_bsum[blockIdx.x];
        g_start[i] = excl;
        g_inv[i] = 1.0f / fmaxf((float)d, 1.0f);
        g_fill[i] = 0;
    }
}

// 8 edges per thread.
__global__ void place_kernel(const int* __restrict__ src,
                             const int* __restrict__ dst, int E) {
    int t = blockIdx.x * blockDim.x + threadIdx.x;
    int e = t * 8;
    if (e + 8 <= E) {
        int4 d0 = *(const int4*)(dst + e);
        int4 d1 = *(const int4*)(dst + e + 4);
        int4 s0 = *(const int4*)(src + e);
        int4 s1 = *(const int4*)(src + e + 4);
        g_csr[g_start[d0.x] + atomicAdd(&g_fill[d0.x], 1)] = s0.x;
        g_csr[g_start[d0.y] + atomicAdd(&g_fill[d0.y], 1)] = s0.y;
        g_csr[g_start[d0.z] + atomicAdd(&g_fill[d0.z], 1)] = s0.z;
        g_csr[g_start[d0.w] + atomicAdd(&g_fill[d0.w], 1)] = s0.w;
        g_csr[g_start[d1.x] + atomicAdd(&g_fill[d1.x], 1)] = s1.x;
        g_csr[g_start[d1.y] + atomicAdd(&g_fill[d1.y], 1)] = s1.y;
        g_csr[g_start[d1.z] + atomicAdd(&g_fill[d1.z], 1)] = s1.z;
        g_csr[g_start[d1.w] + atomicAdd(&g_fill[d1.w], 1)] = s1.w;
    } else {
        for (int i = e; i < E; i++)
            g_csr[g_start[dst[i]] + atomicAdd(&g_fill[dst[i]], 1)] = src[i];
    }
}

// ---------------- conversions + deg zero (fused) ----------------

__global__ void convert_kernel(const float* __restrict__ x,
                               const float* __restrict__ W1l,
                               const float* __restrict__ W1r,
                               const float* __restrict__ W2l,
                               const float* __restrict__ W2r, int N) {
    int t = blockIdx.x * blockDim.x + threadIdx.x;
    if (t < N) g_deg[t] = 0;
    if (t < N * 32) {
        float2 v = ((const float2*)x)[t];
        g_xh[t] = __floats2half2_rn(v.x, v.y);
    }
    if (t < 4096) g_W1lh[t] = __float2half_rn(W1l[t]);
    else if (t < 8192) g_W1rh[t - 4096] = __float2half_rn(W1r[t - 4096]);
    else if (t < 10240) g_W2lh[t - 8192] = __float2half_rn(W2l[t - 8192]);
    else if (t < 12288) g_W2rh[t - 10240] = __float2half_rn(W2r[t - 10240]);
}

// ---------------- layer-1 gather (fp16 mean) ----------------

// 4 nodes per warp, 8 lanes per node, lane holds one int4 (16B) of 128B row.
__global__ void gather64_v4_kernel(int N) {
    int g = blockIdx.x * blockDim.x + threadIdx.x;
    int warp = g >> 5;
    int lane = g & 31;
    int node = warp * 4 + (lane >> 3);
    int lg = lane & 7;
    if (node >= N) return;
    int s0 = g_start[node];
    int d = g_deg[node];
    const int4* xrow = (const int4*)g_xh;
    float a0 = 0.f, a1 = 0.f, a2 = 0.f, a3 = 0.f;
    float a4 = 0.f, a5 = 0.f, a6 = 0.f, a7 = 0.f;
    int j = 0;
    for (; j + 4 <= d; j += 4) {
        int si[4];
#pragma unroll
        for (int u = 0; u < 4; u++) si[u] = g_csr[s0 + j + u];
        int4 v[4];
#pragma unroll
        for (int u = 0; u < 4; u++) v[u] = xrow[si[u] * 8 + lg];
#pragma unroll
        for (int u = 0; u < 4; u++) {
            float2 f0 = __half22float2(*(__half2*)&v[u].x);
            float2 f1 = __half22float2(*(__half2*)&v[u].y);
            float2 f2 = __half22float2(*(__half2*)&v[u].z);
            float2 f3 = __half22float2(*(__half2*)&v[u].w);
            a0 += f0.x; a1 += f0.y; a2 += f1.x; a3 += f1.y;
            a4 += f2.x; a5 += f2.y; a6 += f3.x; a7 += f3.y;
        }
    }
    for (; j < d; j++) {
        int4 v = xrow[g_csr[s0 + j] * 8 + lg];
        float2 f0 = __half22float2(*(__half2*)&v.x);
        float2 f1 = __half22float2(*(__half2*)&v.y);
        float2 f2 = __half22float2(*(__half2*)&v.z);
        float2 f3 = __half22float2(*(__half2*)&v.w);
        a0 += f0.x; a1 += f0.y; a2 += f1.x; a3 += f1.y;
        a4 += f2.x; a5 += f2.y; a6 += f3.x; a7 += f3.y;
    }
    float iv = g_inv[node];
    __half2 o0 = __floats2half2_rn(a0 * iv, a1 * iv);
    __half2 o1 = __floats2half2_rn(a2 * iv, a3 * iv);
    __half2 o2 = __floats2half2_rn(a4 * iv, a5 * iv);
    __half2 o3 = __floats2half2_rn(a6 * iv, a7 * iv);
    int4 ov;
    ov.x = *(int*)&o0; ov.y = *(int*)&o1; ov.z = *(int*)&o2; ov.w = *(int*)&o3;
    ((int4*)g_mh)[node * 8 + lg] = ov;
}

// ---------------- layer-2 gather + combine + layer-3 dots (fused) ----------------
// 8 nodes per warp, 4 lanes per node, lane holds one int4 (16B) of the 64B row.
// Epilogue: h2 = relu(mean + b2 + r2); p3 = h2.W3l; r3 = h2.W3r (4-lane reduce).
__global__ void gather32_fused_kernel(const float* __restrict__ b2,
                                      const float* __restrict__ W3l,
                                      const float* __restrict__ W3r, int N) {
    __shared__ float sb[32], s3l[32], s3r[32];
    if (threadIdx.x < 32) {
        sb[threadIdx.x] = b2[threadIdx.x];
        s3l[threadIdx.x] = W3l[threadIdx.x];
        s3r[threadIdx.x] = W3r[threadIdx.x];
    }
    __syncthreads();
    int g = blockIdx.x * blockDim.x + threadIdx.x;
    int warp = g >> 5;
    int lane = g & 31;
    int node = warp * 8 + (lane >> 2);
    int lg = lane & 3;
    if (node >= N) return;
    int s0 = g_start[node];
    int d = g_deg[node];
    const int4* prow = (const int4*)g_p2;
    float a0 = 0.f, a1 = 0.f, a2 = 0.f, a3 = 0.f;
    float a4 = 0.f, a5 = 0.f, a6 = 0.f, a7 = 0.f;
    int j = 0;
    for (; j + 4 <= d; j += 4) {
        int si[4];
#pragma unroll
        for (int u = 0; u < 4; u++) si[u] = g_csr[s0 + j + u];
        int4 v[4];
#pragma unroll
        for (int u = 0; u < 4; u++) v[u] = prow[si[u] * 4 + lg];
#pragma unroll
        for (int u = 0; u < 4; u++) {
            float2 f0 = __half22float2(*(__half2*)&v[u].x);
            float2 f1 = __half22float2(*(__half2*)&v[u].y);
            float2 f2 = __half22float2(*(__half2*)&v[u].z);
            float2 f3 = __half22float2(*(__half2*)&v[u].w);
            a0 += f0.x; a1 += f0.y; a2 += f1.x; a3 += f1.y;
            a4 += f2.x; a5 += f2.y; a6 += f3.x; a7 += f3.y;
        }
    }
    for (; j < d; j++) {
        int4 v = prow[g_csr[s0 + j] * 4 + lg];
        float2 f0 = __half22float2(*(__half2*)&v.x);
        float2 f1 = __half22float2(*(__half2*)&v.y);
        float2 f2 = __half22float2(*(__half2*)&v.z);
        float2 f3 = __half22float2(*(__half2*)&v.w);
        a0 += f0.x; a1 += f0.y; a2 += f1.x; a3 += f1.y;
        a4 += f2.x; a5 += f2.y; a6 += f3.x; a7 += f3.y;
    }
    // Epilogue: this lane owns h2 columns [lg*8, lg*8+8).
    float iv = g_inv[node];
    int cb = lg * 8;
    const float4* r2p = (const float4*)(g_r2 + node * 32 + cb);
    float4 r2a = r2p[0], r2b = r2p[1];
    float h[8];
    h[0] = fmaxf(a0 * iv + sb[cb + 0] + r2a.x, 0.f);
    h[1] = fmaxf(a1 * iv + sb[cb + 1] + r2a.y, 0.f);
    h[2] = fmaxf(a2 * iv + sb[cb + 2] + r2a.z, 0.f);
    h[3] = fmaxf(a3 * iv + sb[cb + 3] + r2a.w, 0.f);
    h[4] = fmaxf(a4 * iv + sb[cb + 4] + r2b.x, 0.f);
    h[5] = fmaxf(a5 * iv + sb[cb + 5] + r2b.y, 0.f);
    h[6] = fmaxf(a6 * iv + sb[cb + 6] + r2b.z, 0.f);
    h[7] = fmaxf(a7 * iv + sb[cb + 7] + r2b.w, 0.f);
    float pa = 0.f, pr = 0.f;
#pragma unroll
    for (int q = 0; q < 8; q++) {
        pa = fmaf(h[q], s3l[cb + q], pa);
        pr = fmaf(h[q], s3r[cb + q], pr);
    }
    unsigned m = __activemask();
    pa += __shfl_xor_sync(m, pa, 1);
    pr += __shfl_xor_sync(m, pr, 1);
    pa += __shfl_xor_sync(m, pa, 2);
    pr += __shfl_xor_sync(m, pr, 2);
    if (lg == 0) {
        g_p3[node] = pa;
        g_r3[node] = pr;
    }
}

// ---------------- tensor-core fused dense chain ----------------

__global__ void dense_wmma_kernel(const float* __restrict__ b1, int N) {
    __shared__ float  sF[64 * 64];
    __shared__ __half sH[64 * 64];
    int warp = threadIdx.x >> 5;
    int base = blockIdx.x * 64;
    const __half* mh = (const __half*)g_mh;
    const __half* xh = (const __half*)g_xh;

    wmma::fragment<wmma::accumulator, 16, 16, 16, float> acc;
    wmma::fragment<wmma::matrix_a, 16, 16, 16, __half, wmma::row_major> fa;
    wmma::fragment<wmma::matrix_b, 16, 16, 16, __half, wmma::row_major> fb;

    int arow = (base + warp * 16) * 64;
#pragma unroll
    for (int nt = 0; nt < 4; nt++) {
        wmma::fill_fragment(acc, 0.f);
#pragma unroll
        for (int k = 0; k < 4; k++) {
            wmma::load_matrix_sync(fa, mh + arow + k * 16, 64);
            wmma::load_matrix_sync(fb, g_W1lh + (k * 16) * 64 + nt * 16, 64);
            wmma::mma_sync(acc, fa, fb, acc);
            wmma::load_matrix_sync(fa, xh + arow + k * 16, 64);
            wmma::load_matrix_sync(fb, g_W1rh + (k * 16) * 64 + nt * 16, 64);
            wmma::mma_sync(acc, fa, fb, acc);
        }
        wmma::store_matrix_sync(sF + (warp * 16) * 64 + nt * 16, acc, 64, wmma::mem_row_major);
    }
    __syncthreads();
    for (int i = threadIdx.x; i < 64 * 64; i += blockDim.x) {
        int col = i & 63;
        sH[i] = __float2half_rn(fmaxf(sF[i] + b1[col], 0.f));
    }
    __syncthreads();

#pragma unroll
    for (int nt = 0; nt < 2; nt++) {
        wmma::fill_fragment(acc, 0.f);
#pragma unroll
        for (int k = 0; k < 4; k++) {
            wmma::load_matrix_sync(fa, sH + (warp * 16) * 64 + k * 16, 64);
            wmma::load_matrix_sync(fb, g_W2lh + (k * 16) * 32 + nt * 16, 32);
            wmma::mma_sync(acc, fa, fb, acc);
        }
        wmma::store_matrix_sync(sF + (warp * 16) * 32 + nt * 16, acc, 32, wmma::mem_row_major);
    }
    __syncthreads();
    for (int i = threadIdx.x; i < 64 * 32; i += blockDim.x) {
        int node = base + (i >> 5);
        if (node < N) ((__half*)g_p2)[node * 32 + (i & 31)] = __float2half_rn(sF[i]);
    }
    __syncthreads();

#pragma unroll
    for (int nt = 0; nt < 2; nt++) {
        wmma::fill_fragment(acc, 0.f);
#pragma unroll
        for (int k = 0; k < 4; k++) {
            wmma::load_matrix_sync(fa, sH + (warp * 16) * 64 + k * 16, 64);
            wmma::load_matrix_sync(fb, g_W2rh + (k * 16) * 32 + nt * 16, 32);
            wmma::mma_sync(acc, fa, fb, acc);
        }
        wmma::store_matrix_sync(sF + (warp * 16) * 32 + nt * 16, acc, 32, wmma::mem_row_major);
    }
    __syncthreads();
    for (int i = threadIdx.x; i < 64 * 32; i += blockDim.x) {
        int node = base + (i >> 5);
        if (node < N) g_r2[node * 32 + (i & 31)] = sF[i];
    }
}

// Final: one warp per node, lanes parallel over edges; fused sigmoid.
__global__ void gather1_final_kernel(const float* __restrict__ b3,
                                     float* __restrict__ out, int N) {
    int g = blockIdx.x * blockDim.x + threadIdx.x;
    int node = g >> 5;
    int lane = g & 31;
    if (node >= N) return;
    int s0 = g_start[node];
    int d = g_deg[node];
    float acc = 0.f;
    for (int j = lane; j < d; j += 32) acc += g_p3[g_csr[s0 + j]];
#pragma unroll
    for (int off = 16; off; off >>= 1) acc += __shfl_xor_sync(0xffffffffu, acc, off);
    if (lane == 0) {
        float v = acc * g_inv[node] + b3[0] + g_r3[node];
        out[node] = 1.0f / (1.0f + expf(-v));
    }
}

// ---------------- launch ----------------

extern "C" void kernel_launch(void* const* d_in, const int* in_sizes, int n_in,
                              void* d_out, int out_size) {
    const float* x   = (const float*)d_in[0];
    const int*   ei  = (const int*)d_in[1];   // int32 (JAX x64 disabled)
    const float* W1l = (const float*)d_in[2];
    const float* b1  = (const float*)d_in[3];
    const float* W1r = (const float*)d_in[4];
    const float* W2l = (const float*)d_in[5];
    const float* b2  = (const float*)d_in[6];
    const float* W2r = (const float*)d_in[7];
    const float* W3l = (const float*)d_in[8];
    const float* b3  = (const float*)d_in[9];
    const float* W3r = (const float*)d_in[10];
    float* out = (float*)d_out;

    int N = in_sizes[0] / 64;
    int E = in_sizes[1] / 2;
    const int* src = ei;
    const int* dst = ei + E;

    const int TB = 256;
    auto blocks = [](long long n, int tb) { return (int)((n + tb - 1) / tb); };
    int nb = (N + SCAN_TB - 1) / SCAN_TB;
    int E8 = (E + 7) / 8;

    // convert also zeroes g_deg; must precede hist.
    convert_kernel<<<blocks((long long)N * 32, TB), TB>>>(x, W1l, W1r, W2l, W2r, N);
    hist_kernel<<<blocks(E8, TB), TB>>>(dst, E);
    blocksum_kernel<<<nb, SCAN_TB>>>(N);
    scan_bsums_kernel<<<1, 128>>>(nb);
    starts_kernel<<<nb, SCAN_TB>>>(N);
    place_kernel<<<blocks(E8, TB), TB>>>(src, dst, E);

    // ---- layer 1: wide gather -> fp16 mean; wmma dense chain ----
    gather64_v4_kernel<<<blocks((long long)N * 8, TB), TB>>>(N);
    dense_wmma_kernel<<<(N + 63) / 64, 128>>>(b1, N);

    // ---- layer 2: fused gather + combine + layer-3 dots ----
    gather32_fused_kernel<<<blocks((long long)N * 4, TB), TB>>>(b2, W3l, W3r, N);

    // ---- layer 3: scalar gather + sigmoid ----
    gather1_final_kernel<<<blocks((long long)N * 32, TB), TB>>>(b3, out, N);
}